// round 7
// baseline (speedup 1.0000x reference)
#include <cuda_runtime.h>
#include <cstdint>
#include <math.h>

#define PTS    8192
#define NB     4
#define NSETS  8                // (batch, set): even = yhat, odd = y
#define NX     64
#define NY     64
#define NCELL  (NX * NY)        // snake-ordered cells
#define GMIN   (-8.0f)
#define GINV   4.0f             // 1 / 0.25
#define PADP   64               // pad pairs each side
#define NPAIR  (PADP + PTS / 2 + PADP)   // 4224 pairs
#define NQBLK  (NSETS * 64)     // 512 search blocks

// Pair-packed cell-sorted points: pair j occupies two float4s:
//   g_pp[2j]   = {x0,x1,y0,y1}   g_pp[2j+1] = {z0,z1,s0,s1}   (s = |p|^2)
// Pads: s = 3e38 so they never win a min.
__device__ float4 g_pp[NSETS][NPAIR * 2];
__device__ float4 g_q[NSETS][PTS];          // cell-sorted queries (x,y,z,|q|^2)
__device__ int    g_hist[NSETS][NCELL];
__device__ int    g_start[NSETS][NCELL + 1];
__device__ float  g_part[NQBLK];

// snake cell id: row-major in y, x direction alternates per row
__device__ __forceinline__ int cell_of(float x, float y) {
    int bx = (int)fminf(fmaxf((x - GMIN) * GINV, 0.f), 63.f);
    int by = (int)fminf(fmaxf((y - GMIN) * GINV, 0.f), 63.f);
    return by * NX + ((by & 1) ? (NX - 1 - bx) : bx);
}

#define FMA_F32X2(d, a, b, c) \
    asm("fma.rn.f32x2 %0, %1, %2, %3;" : "=l"(d) : "l"(a), "l"(b), "l"(c))
#define UNPACK_F32X2(lo, hi, v) \
    asm("mov.b64 {%0, %1}, %2;" : "=f"(lo), "=f"(hi) : "l"(v))

__device__ __forceinline__ unsigned long long pack2f(float lo, float hi) {
    unsigned long long r;
    asm("mov.b64 %0, {%1, %2};" : "=l"(r) : "f"(lo), "f"(hi));
    return r;
}

// ---------------------------------------------------------------------------
__global__ void zero_kernel() {
    int i = blockIdx.x * blockDim.x + threadIdx.x;   // 32768 = 8*4096
    ((int*)g_hist)[i] = 0;
}

// 128 blocks x 512 : one point per thread, count cells
__global__ __launch_bounds__(512)
void hist_kernel(const float* __restrict__ yhat, const float* __restrict__ y)
{
    int gid = blockIdx.x * 512 + threadIdx.x;     // 0..65535
    int g = gid >> 13, i = gid & 8191;
    const float* src = ((g & 1) ? y : yhat) + (size_t)(g >> 1) * PTS * 3;
    float x = src[3 * i], yy = src[3 * i + 1];
    atomicAdd(&g_hist[g][cell_of(x, yy)], 1);
}

// 8 blocks (one per set) x 512 : exclusive scan of 4096 cells into smem
// cursors + g_start, write pads, then scatter this set's 8192 points into
// pair-packed cell order. Within-cell order is nondeterministic (atomics);
// the final exact-min result is order-independent.
__global__ __launch_bounds__(512)
void scanscatter_kernel(const float* __restrict__ yhat, const float* __restrict__ y)
{
    __shared__ int cursor[NCELL];
    __shared__ int wsum[16];
    const int g = blockIdx.x, t = threadIdx.x;
    const float* src = ((g & 1) ? y : yhat) + (size_t)(g >> 1) * PTS * 3;

    // scan: 8 cells per thread + 2-level warp scan
    const int base = t * 8;
    int v[8], tot = 0;
#pragma unroll
    for (int j = 0; j < 8; ++j) { v[j] = g_hist[g][base + j]; tot += v[j]; }
    const int lane = t & 31, warp = t >> 5;
    int inc = tot;
#pragma unroll
    for (int o = 1; o < 32; o <<= 1) {
        int u = __shfl_up_sync(0xffffffffu, inc, o);
        if (lane >= o) inc += u;
    }
    if (lane == 31) wsum[warp] = inc;
    __syncthreads();
    if (warp == 0) {
        int wv = (lane < 16) ? wsum[lane] : 0;
#pragma unroll
        for (int o = 1; o < 16; o <<= 1) {
            int u = __shfl_up_sync(0xffffffffu, wv, o);
            if (lane >= o) wv += u;
        }
        if (lane < 16) wsum[lane] = wv;
    }
    __syncthreads();
    int excl = inc - tot + ((warp > 0) ? wsum[warp - 1] : 0);
#pragma unroll
    for (int j = 0; j < 8; ++j) {
        g_start[g][base + j] = excl;
        cursor[base + j]     = excl;
        excl += v[j];
    }
    if (t == 0) g_start[g][NCELL] = PTS;

    // pads (pair indices [0,64) and [64+4096, 4224))
    if (t < PADP) {
        g_pp[g][2 * t]     = make_float4(0.f, 0.f, 0.f, 0.f);
        g_pp[g][2 * t + 1] = make_float4(0.f, 0.f, 3.0e38f, 3.0e38f);
        int o = PADP + PTS / 2 + t;
        g_pp[g][2 * o]     = make_float4(0.f, 0.f, 0.f, 0.f);
        g_pp[g][2 * o + 1] = make_float4(0.f, 0.f, 3.0e38f, 3.0e38f);
    }
    __syncthreads();

    // scatter
#pragma unroll
    for (int j = 0; j < 16; ++j) {
        int i = j * 512 + t;
        float x = src[3 * i], yy = src[3 * i + 1], z = src[3 * i + 2];
        int pos = atomicAdd(&cursor[cell_of(x, yy)], 1);
        float s = x * x + yy * yy + z * z;
        int pj = PADP + (pos >> 1), sl = pos & 1;
        float* pA = (float*)&g_pp[g][2 * pj];
        pA[sl]     = x;
        pA[2 + sl] = yy;
        pA[4 + sl] = z;
        pA[6 + sl] = s;
        g_q[g][pos] = make_float4(x, yy, z, s);
    }
}

// ---------------------------------------------------------------------------
// search: warp-cooperative exact NN, 2D snake-cell pruning, vote-free.
//   bestm = min over p of (|p|^2 - 2 q.p);  d^2 = bestm + |q|^2 (clamped).
//   Phase 1: fixed 32 pairs (64 pts) around warp's anchor-cell start.
//   Window:  r = sqrt(max-lane clamp(best+|q|^2,0)); cell box from lane
//            min/max (x,y) +- r — any excluded point has per-axis gap > r
//            >= sqrt(lane best) for every lane, so it cannot win. Exact.
//   Phase 2: per y-row contiguous snake runs, fixed-trip, no votes.
//   Rescanning points (overlap / pair-rounding) is harmless: idempotent min.
// ---------------------------------------------------------------------------
__global__ __launch_bounds__(128)
void search_kernel()
{
    const int bid = blockIdx.x;
    const int grp = bid >> 6;       // (b,set) 0..7
    const int sub = bid & 63;
    const int qset = grp;
    const int pset = grp ^ 1;

    const int t = threadIdx.x, warp = t >> 5, lane = t & 31;
    const int qi = (sub * 4 + warp) * 32 + lane;

    float4 q = __ldg(&g_q[qset][qi]);
    const float qx = q.x, qy = q.y, sqq = q.w;
    const unsigned long long q2x = pack2f(-2.f * q.x, -2.f * q.x);
    const unsigned long long q2y = pack2f(-2.f * q.y, -2.f * q.y);
    const unsigned long long q2z = pack2f(-2.f * q.z, -2.f * q.z);

    // anchor cell from lane 16 (queries are snake-cell-coherent)
    float cx = __shfl_sync(0xffffffffu, qx, 16);
    float cy = __shfl_sync(0xffffffffu, qy, 16);
    const int k0p = PADP + (__ldg(&g_start[pset][cell_of(cx, cy)]) >> 1);

    float bestA = 3.0e38f, bestB = 3.0e38f;
    const float4* pp = &g_pp[pset][0];

#define PROC_PAIR(jj) do {                                                \
        int _j = (jj);                                                    \
        float4 A = __ldg(pp + 2 * _j);                                    \
        float4 Bv = __ldg(pp + 2 * _j + 1);                               \
        unsigned long long xx = pack2f(A.x, A.y);                         \
        unsigned long long yy = pack2f(A.z, A.w);                         \
        unsigned long long zz = pack2f(Bv.x, Bv.y);                       \
        unsigned long long ww = pack2f(Bv.z, Bv.w);                       \
        unsigned long long d;                                             \
        FMA_F32X2(d, q2z, zz, ww);                                        \
        FMA_F32X2(d, q2y, yy, d);                                         \
        FMA_F32X2(d, q2x, xx, d);                                         \
        float lo, hi;                                                     \
        UNPACK_F32X2(lo, hi, d);                                          \
        bestA = fminf(bestA, lo);                                         \
        bestB = fminf(bestB, hi);                                         \
    } while (0)

    // ---- phase 1: fixed 32 pairs around anchor ----
#pragma unroll 4
    for (int jj = 0; jj < 32; ++jj) PROC_PAIR(k0p - 8 + jj);

    // ---- window from phase-1 best ----
    float r2 = fmaxf(fminf(bestA, bestB) + sqq, 0.f);
    float xmn = qx, xmx = qx, ymn = qy, ymx = qy;
#pragma unroll
    for (int o = 16; o > 0; o >>= 1) {
        r2  = fmaxf(r2,  __shfl_xor_sync(0xffffffffu, r2,  o));
        xmn = fminf(xmn, __shfl_xor_sync(0xffffffffu, xmn, o));
        xmx = fmaxf(xmx, __shfl_xor_sync(0xffffffffu, xmx, o));
        ymn = fminf(ymn, __shfl_xor_sync(0xffffffffu, ymn, o));
        ymx = fmaxf(ymx, __shfl_xor_sync(0xffffffffu, ymx, o));
    }
    float r = sqrtf(r2);
    int bx0 = (int)fminf(fmaxf((xmn - r - GMIN) * GINV, 0.f), 63.f);
    int bx1 = (int)fminf(fmaxf((xmx + r - GMIN) * GINV, 0.f), 63.f);
    int by0 = (int)fminf(fmaxf((ymn - r - GMIN) * GINV, 0.f), 63.f);
    int by1 = (int)fminf(fmaxf((ymx + r - GMIN) * GINV, 0.f), 63.f);

    // ---- phase 2: snake row runs ----
    for (int by = by0; by <= by1; ++by) {
        int c0 = (by & 1) ? (NX - 1 - bx1) : bx0;
        int c1 = (by & 1) ? (NX - 1 - bx0) : bx1;
        int is = __ldg(&g_start[pset][by * NX + c0]);
        int ie = __ldg(&g_start[pset][by * NX + c1 + 1]);
        int jp0 = PADP + (is >> 1);
        int jp1 = PADP + ((ie + 1) >> 1);
#pragma unroll 4
        for (int j = jp0; j < jp1; ++j) PROC_PAIR(j);
    }

    float best = fmaxf(fminf(bestA, bestB) + sqq, 0.f);

    // block sum of mins
#pragma unroll
    for (int o = 16; o > 0; o >>= 1)
        best += __shfl_down_sync(0xffffffffu, best, o);
    __shared__ float bsum[4];
    if (lane == 0) bsum[warp] = best;
    __syncthreads();
    if (t == 0)
        g_part[bid] = bsum[0] + bsum[1] + bsum[2] + bsum[3];
}

// loss = sum(all 2*B*PTS mins) / (B*PTS);  out = sqrt(0.5 * loss)
__global__ void final_kernel(float* __restrict__ out)
{
    const int t = threadIdx.x;   // 512
    double s = (double)g_part[t];
#pragma unroll
    for (int o = 16; o > 0; o >>= 1)
        s += __shfl_down_sync(0xffffffffu, s, o);
    __shared__ double sh[16];
    if ((t & 31) == 0) sh[t >> 5] = s;
    __syncthreads();
    if (t == 0) {
        double tot = 0.0;
#pragma unroll
        for (int w = 0; w < 16; ++w) tot += sh[w];
        out[0] = (float)sqrt(0.5 * tot / (double)(NB * PTS));
    }
}

extern "C" void kernel_launch(void* const* d_in, const int* in_sizes, int n_in,
                              void* d_out, int out_size)
{
    const float* yhat = (const float*)d_in[0];   // [B, N, 3]
    const float* y    = (const float*)d_in[1];   // [B, M, 3]
    (void)in_sizes; (void)n_in; (void)out_size;

    zero_kernel<<<32, 1024>>>();
    hist_kernel<<<128, 512>>>(yhat, y);
    scanscatter_kernel<<<NSETS, 512>>>(yhat, y);
    search_kernel<<<NQBLK, 128>>>();
    final_kernel<<<1, 512>>>((float*)d_out);
}